// round 4
// baseline (speedup 1.0000x reference)
#include <cuda_runtime.h>
#include <math.h>

#define T_STEPS 512
#define BATCH   128
#define HID     512
#define GATES   1536
#define MROWS   (T_STEPS*BATCH)

__device__ float g_xW[(size_t)MROWS * GATES];   // 402 MB scratch
__device__ int          g_cnt4[4 * 32];          // one counter per row-group, 128B apart
__device__ volatile int g_sense4[4 * 32];

__device__ __forceinline__ unsigned long long packf2(float lo, float hi) {
    unsigned long long r;
    asm("mov.b64 %0, {%1, %2};" : "=l"(r) : "f"(lo), "f"(hi));
    return r;
}
__device__ __forceinline__ void unpackf2(unsigned long long v, float& lo, float& hi) {
    asm("mov.b64 {%0, %1}, %2;" : "=f"(lo), "=f"(hi) : "l"(v));
}
__device__ __forceinline__ void fma2(unsigned long long& acc,
                                     unsigned long long a, unsigned long long b) {
    asm("fma.rn.f32x2 %0, %1, %2, %0;" : "+l"(acc) : "l"(a), "l"(b));
}
__device__ __forceinline__ float sigm(float x)  { return 1.0f / (1.0f + __expf(-x)); }
__device__ __forceinline__ float tanhx(float x) { return 1.0f - 2.0f / (__expf(2.0f * x) + 1.0f); }

// ============================ Phase 1: xW GEMM =============================
__global__ __launch_bounds__(256, 2)
void xw_gemm(const float* __restrict__ A, const float* __restrict__ B,
             const float* __restrict__ bi)
{
    __shared__ __align__(16) float As[8][132];
    __shared__ __align__(16) float Bs[8][128];
    const int tid = threadIdx.x;
    const int mb = blockIdx.y * 128, nb = blockIdx.x * 128;
    const int arow = tid >> 1, ak = (tid & 1) * 4;
    const int brow = tid >> 5, bcol = (tid & 31) * 4;
    const int ty8 = (tid >> 4) * 8, tx8 = (tid & 15) * 8;

    unsigned long long acc[32];
#pragma unroll
    for (int i = 0; i < 32; i++) acc[i] = 0ull;

    const float* Ap = A + (size_t)(mb + arow) * HID + ak;
    const float* Bp = B + (size_t)brow * GATES + nb + bcol;

    for (int kt = 0; kt < 64; kt++) {
        float4 ra = *(const float4*)(Ap + kt * 8);
        float4 rb = *(const float4*)(Bp + (size_t)kt * 8 * GATES);
        As[ak + 0][arow] = ra.x; As[ak + 1][arow] = ra.y;
        As[ak + 2][arow] = ra.z; As[ak + 3][arow] = ra.w;
        *(float4*)&Bs[brow][bcol] = rb;
        __syncthreads();
#pragma unroll
        for (int kk = 0; kk < 8; kk++) {
            float4 a0 = *(const float4*)&As[kk][ty8];
            float4 a1 = *(const float4*)&As[kk][ty8 + 4];
            ulonglong2 b0 = *(const ulonglong2*)&Bs[kk][tx8];
            ulonglong2 b1 = *(const ulonglong2*)&Bs[kk][tx8 + 4];
            float ar[8] = {a0.x, a0.y, a0.z, a0.w, a1.x, a1.y, a1.z, a1.w};
#pragma unroll
            for (int i = 0; i < 8; i++) {
                unsigned long long av = packf2(ar[i], ar[i]);
                fma2(acc[i*4+0], av, b0.x); fma2(acc[i*4+1], av, b0.y);
                fma2(acc[i*4+2], av, b1.x); fma2(acc[i*4+3], av, b1.y);
            }
        }
        __syncthreads();
    }
    float4 c0 = *(const float4*)&bi[nb + tx8];
    float4 c1 = *(const float4*)&bi[nb + tx8 + 4];
#pragma unroll
    for (int i = 0; i < 8; i++) {
        float4 o0, o1;
        unpackf2(acc[i*4+0], o0.x, o0.y); unpackf2(acc[i*4+1], o0.z, o0.w);
        unpackf2(acc[i*4+2], o1.x, o1.y); unpackf2(acc[i*4+3], o1.z, o1.w);
        o0.x += c0.x; o0.y += c0.y; o0.z += c0.z; o0.w += c0.w;
        o1.x += c1.x; o1.y += c1.y; o1.z += c1.z; o1.w += c1.w;
        size_t off = (size_t)(mb + ty8 + i) * GATES + nb + tx8;
        *(float4*)&g_xW[off] = o0; *(float4*)&g_xW[off + 4] = o1;
    }
}

// ============================ Phase 2: GRU scan ============================
// ws layout: ws[k*64 + cu*8 + m], m = {r0,r1,z0,z1,n0,n1,pad,pad}
// unit0 = j0g + 2*cu, unit1 = unit0 + 1
#define WSTR 64
#define HSTR 520
#define WSF  (HID * WSTR)                       // 32768 floats = 131072 B
#define SCAN_SMEM ((WSF + 32 * HSTR) * 4)       // 197,632 B

// Barrier over the 32 blocks of one row-group (rc). Sense-reversing; after
// 512 flips state returns to 0 -> deterministic across graph replays.
__device__ __forceinline__ void groupbar(int rc) {
    __threadfence();
    __syncthreads();
    if (threadIdx.x == 0) {
        int* cnt = &g_cnt4[rc * 32];
        volatile int* sns = &g_sense4[rc * 32];
        int s = *sns;
        if (atomicAdd(cnt, 1) == 31) {
            *cnt = 0;
            __threadfence();
            *sns = s ^ 1;
        } else {
            while (*sns == s) { }
        }
    }
    __syncthreads();
    __threadfence();
}

__global__ __launch_bounds__(256, 1)
void gru_scan(const unsigned int* __restrict__ resets,
              const float* __restrict__ Wh,
              const float* __restrict__ bhn,
              float* __restrict__ out)
{
    extern __shared__ __align__(16) float sm[];
    float* ws  = sm;            // [512][64]
    float* hsh = sm + WSF;      // [32][520]
    __shared__ unsigned int rfl[32];

    const int bx = blockIdx.x;
    const int rc = bx & 3, jc = bx >> 2;
    const int r0 = rc * 32, j0g = jc * 16;
    const int tid = threadIdx.x;
    const int row = tid >> 3, cu = tid & 7;
    const int jg0 = j0g + 2 * cu;
    const int bglob = r0 + row;

    // one-time: load + repack this block's Wh slice
    for (int idx = tid; idx < HID * 48; idx += 256) {
        int k = idx / 48, c = idx - k * 48;
        int tcu = c / 6, m = c - tcu * 6;
        int g = m >> 1, jl = m & 1;
        ws[k * WSTR + tcu * 8 + m] = Wh[(size_t)k * GATES + g * HID + j0g + 2 * tcu + jl];
    }
    const float2 bh = *(const float2*)&bhn[jg0];
    if (tid < 32) rfl[tid] = 1u;    // t=0 behaves as reset
    __syncthreads();

    // prefetch x gates for t=0
    const float* xrow = g_xW + (size_t)bglob * GATES;
    float2 xr = *(const float2*)(xrow + jg0);
    float2 xz = *(const float2*)(xrow + HID + jg0);
    float2 xn = *(const float2*)(xrow + 2 * HID + jg0);

    for (int t = 0; t < T_STEPS; t++) {
        // ---- stage h_prev into smem (flat, coalesced, conflict-free) ----
        if (t == 0) {
            float4 z4 = make_float4(0.f, 0.f, 0.f, 0.f);
#pragma unroll
            for (int i = 0; i < 16; i++) {
                int j = i * 256 + tid;
                *(float4*)&hsh[(j >> 7) * HSTR + (j & 127) * 4] = z4;
            }
        } else {
            const float* hp = out + (size_t)(t - 1) * (BATCH * HID) + (size_t)r0 * HID;
#pragma unroll
            for (int i = 0; i < 16; i++) {
                int j = i * 256 + tid;
                float4 v = *(const float4*)(hp + (size_t)j * 4);
                if (rfl[j >> 7]) v = make_float4(0.f, 0.f, 0.f, 0.f);
                *(float4*)&hsh[(j >> 7) * HSTR + (j & 127) * 4] = v;
            }
        }
        __syncthreads();

        // ---- prefetch next step's x gates + reset flags (hide latency) ----
        float2 nxr = xr, nxz = xz, nxn = xn;
        if (t + 1 < T_STEPS) {
            const float* nx = g_xW + (size_t)((t + 1) * BATCH + bglob) * GATES;
            nxr = *(const float2*)(nx + jg0);
            nxz = *(const float2*)(nx + HID + jg0);
            nxn = *(const float2*)(nx + 2 * HID + jg0);
            if (tid < 32) rfl[tid] = resets[(t + 1) * BATCH + r0 + tid];
        }

        // ---- recurrent GEMM: 6 outputs/thread, split-k accumulators ----
        unsigned long long aR0 = 0ull, aZ0 = 0ull, aN0 = 0ull;
        unsigned long long aR1 = 0ull, aZ1 = 0ull, aN1 = 0ull;
        const float* hr_ = &hsh[row * HSTR];
        const float* wb  = ws + cu * 8;
#pragma unroll 2
        for (int k4 = 0; k4 < HID / 4; k4++) {
            float4 h4 = *(const float4*)(hr_ + k4 * 4);
            const float* w = wb + (k4 * 4) * WSTR;
            {
                unsigned long long av = packf2(h4.x, h4.x);
                ulonglong2 w01 = *(const ulonglong2*)(w);
                unsigned long long w2 = *(const unsigned long long*)(w + 4);
                fma2(aR0, av, w01.x); fma2(aZ0, av, w01.y); fma2(aN0, av, w2);
            }
            {
                unsigned long long av = packf2(h4.y, h4.y);
                ulonglong2 w01 = *(const ulonglong2*)(w + WSTR);
                unsigned long long w2 = *(const unsigned long long*)(w + WSTR + 4);
                fma2(aR1, av, w01.x); fma2(aZ1, av, w01.y); fma2(aN1, av, w2);
            }
            {
                unsigned long long av = packf2(h4.z, h4.z);
                ulonglong2 w01 = *(const ulonglong2*)(w + 2 * WSTR);
                unsigned long long w2 = *(const unsigned long long*)(w + 2 * WSTR + 4);
                fma2(aR0, av, w01.x); fma2(aZ0, av, w01.y); fma2(aN0, av, w2);
            }
            {
                unsigned long long av = packf2(h4.w, h4.w);
                ulonglong2 w01 = *(const ulonglong2*)(w + 3 * WSTR);
                unsigned long long w2 = *(const unsigned long long*)(w + 3 * WSTR + 4);
                fma2(aR1, av, w01.x); fma2(aZ1, av, w01.y); fma2(aN1, av, w2);
            }
        }

        float hr0a, hr1a, hz0a, hz1a, hn0a, hn1a;
        float hr0b, hr1b, hz0b, hz1b, hn0b, hn1b;
        unpackf2(aR0, hr0a, hr1a); unpackf2(aZ0, hz0a, hz1a); unpackf2(aN0, hn0a, hn1a);
        unpackf2(aR1, hr0b, hr1b); unpackf2(aZ1, hz0b, hz1b); unpackf2(aN1, hn0b, hn1b);
        float hrs0 = hr0a + hr0b, hrs1 = hr1a + hr1b;
        float hzs0 = hz0a + hz0b, hzs1 = hz1a + hz1b;
        float hns0 = hn0a + hn0b, hns1 = hn1a + hn1b;

        float hp0 = hr_[jg0], hp1 = hr_[jg0 + 1];
        float r0g = sigm(xr.x + hrs0), r1g = sigm(xr.y + hrs1);
        float z0g = sigm(xz.x + hzs0), z1g = sigm(xz.y + hzs1);
        float n0g = tanhx(xn.x + r0g * (hns0 + bh.x));
        float n1g = tanhx(xn.y + r1g * (hns1 + bh.y));
        float2 hnew;
        hnew.x = (1.0f - z0g) * n0g + z0g * hp0;
        hnew.y = (1.0f - z1g) * n1g + z1g * hp1;

        *(float2*)(out + (size_t)(t * BATCH + bglob) * HID + jg0) = hnew;

        xr = nxr; xz = nxz; xn = nxn;

        groupbar(rc);   // sync the 32 blocks sharing this row-group
    }
}

// ================================ Launch ===================================
extern "C" void kernel_launch(void* const* d_in, const int* in_sizes, int n_in,
                              void* d_out, int out_size)
{
    const float*        ins    = (const float*)d_in[0];
    const unsigned int* resets = (const unsigned int*)d_in[1];
    const float*        Wi     = (const float*)d_in[2];
    const float*        bi     = (const float*)d_in[3];
    const float*        Wh     = (const float*)d_in[4];
    const float*        bhn    = (const float*)d_in[5];
    float*              out    = (float*)d_out;

    dim3 g1(GATES / 128, MROWS / 128);
    xw_gemm<<<g1, 256>>>(ins, Wi, bi);

    cudaFuncSetAttribute(gru_scan, cudaFuncAttributeMaxDynamicSharedMemorySize, SCAN_SMEM);
    gru_scan<<<128, 256, SCAN_SMEM>>>(resets, Wh, bhn, out);
}

// round 7
// speedup vs baseline: 1.0949x; 1.0949x over previous
#include <cuda_runtime.h>
#include <math.h>

#define T_STEPS 512
#define BATCH   128
#define HID     512
#define GATES   1536
#define MROWS   (T_STEPS*BATCH)

__device__ float g_xW[(size_t)MROWS * GATES];            // 402 MB scratch
__device__ unsigned long long g_Wt[32 * 256 * 48];       // 3 MB: thread-ordered Wh

typedef unsigned long long ull;

__device__ __forceinline__ ull packf2(float lo, float hi) {
    ull r; asm("mov.b64 %0, {%1, %2};" : "=l"(r) : "f"(lo), "f"(hi)); return r;
}
__device__ __forceinline__ void unpackf2(ull v, float& lo, float& hi) {
    asm("mov.b64 {%0, %1}, %2;" : "=f"(lo), "=f"(hi) : "l"(v));
}
__device__ __forceinline__ void fma2(ull& acc, ull a, ull b) {
    asm("fma.rn.f32x2 %0, %1, %2, %0;" : "+l"(acc) : "l"(a), "l"(b));
}
__device__ __forceinline__ void addf2(ull& a, ull b) {
    asm("add.rn.f32x2 %0, %0, %1;" : "+l"(a) : "l"(b));
}
__device__ __forceinline__ ull shfl2(ull v, int m) {
    unsigned lo, hi;
    asm("mov.b64 {%0, %1}, %2;" : "=r"(lo), "=r"(hi) : "l"(v));
    lo = __shfl_xor_sync(0xffffffffu, lo, m);
    hi = __shfl_xor_sync(0xffffffffu, hi, m);
    ull r; asm("mov.b64 %0, {%1, %2};" : "=l"(r) : "r"(lo), "r"(hi));
    return r;
}
__device__ __forceinline__ float sigm(float x)  { return 1.0f / (1.0f + __expf(-x)); }
__device__ __forceinline__ float tanhx(float x) { return 1.0f - 2.0f / (__expf(2.0f * x) + 1.0f); }

#define SWZ(f) ((f) ^ (((f) >> 3) & 7))

// ============== Prep: Wh -> thread-ordered, unit-pair-packed layout =========
// g_Wt[(jc*256 + tid)*48 + (i*3+g)] = packf2(Wh[(ko*16+i)*G + g*H + u0],
//                                            Wh[..., u0+1]), tid=(up<<5)|ko,
// u0 = jc*16 + 2*up.
__global__ __launch_bounds__(256)
void prep_w(const float* __restrict__ Wh)
{
    int e = blockIdx.x * blockDim.x + threadIdx.x;     // 0 .. 393215
    if (e >= 32 * 256 * 48) return;
    int jc  = e / (256 * 48);
    int r   = e - jc * (256 * 48);
    int tid = r / 48;
    int m   = r - tid * 48;
    int i = m / 3, g = m - i * 3;
    int up = tid >> 5, ko = tid & 31;
    int u0 = jc * 16 + 2 * up;
    float2 wv = *(const float2*)&Wh[(size_t)(ko * 16 + i) * GATES + g * HID + u0];
    g_Wt[e] = packf2(wv.x, wv.y);
}

// ============================ Phase 1: xW GEMM =============================
__global__ __launch_bounds__(256, 2)
void xw_gemm(const float* __restrict__ A, const float* __restrict__ B,
             const float* __restrict__ bi)
{
    __shared__ __align__(16) float As[8][132];
    __shared__ __align__(16) float Bs[8][128];
    const int tid = threadIdx.x;
    const int mb = blockIdx.y * 128, nb = blockIdx.x * 128;
    const int arow = tid >> 1, ak = (tid & 1) * 4;
    const int brow = tid >> 5, bcol = (tid & 31) * 4;
    const int ty8 = (tid >> 4) * 8, tx8 = (tid & 15) * 8;

    ull acc[32];
#pragma unroll
    for (int i = 0; i < 32; i++) acc[i] = 0ull;

    const float* Ap = A + (size_t)(mb + arow) * HID + ak;
    const float* Bp = B + (size_t)brow * GATES + nb + bcol;

    for (int kt = 0; kt < 64; kt++) {
        float4 ra = *(const float4*)(Ap + kt * 8);
        float4 rb = *(const float4*)(Bp + (size_t)kt * 8 * GATES);
        As[ak + 0][arow] = ra.x; As[ak + 1][arow] = ra.y;
        As[ak + 2][arow] = ra.z; As[ak + 3][arow] = ra.w;
        *(float4*)&Bs[brow][bcol] = rb;
        __syncthreads();
#pragma unroll
        for (int kk = 0; kk < 8; kk++) {
            float4 a0 = *(const float4*)&As[kk][ty8];
            float4 a1 = *(const float4*)&As[kk][ty8 + 4];
            ulonglong2 b0 = *(const ulonglong2*)&Bs[kk][tx8];
            ulonglong2 b1 = *(const ulonglong2*)&Bs[kk][tx8 + 4];
            float ar[8] = {a0.x, a0.y, a0.z, a0.w, a1.x, a1.y, a1.z, a1.w};
#pragma unroll
            for (int i = 0; i < 8; i++) {
                ull av = packf2(ar[i], ar[i]);
                fma2(acc[i*4+0], av, b0.x); fma2(acc[i*4+1], av, b0.y);
                fma2(acc[i*4+2], av, b1.x); fma2(acc[i*4+3], av, b1.y);
            }
        }
        __syncthreads();
    }
    float4 c0 = *(const float4*)&bi[nb + tx8];
    float4 c1 = *(const float4*)&bi[nb + tx8 + 4];
#pragma unroll
    for (int i = 0; i < 8; i++) {
        float4 o0, o1;
        unpackf2(acc[i*4+0], o0.x, o0.y); unpackf2(acc[i*4+1], o0.z, o0.w);
        unpackf2(acc[i*4+2], o1.x, o1.y); unpackf2(acc[i*4+3], o1.z, o1.w);
        o0.x += c0.x; o0.y += c0.y; o0.z += c0.z; o0.w += c0.w;
        o1.x += c1.x; o1.y += c1.y; o1.z += c1.z; o1.w += c1.w;
        size_t off = (size_t)(mb + ty8 + i) * GATES + nb + tx8;
        *(float4*)&g_xW[off] = o0; *(float4*)&g_xW[off + 4] = o1;
    }
}

// ======================= Phase 2: one GRU step per launch ==================
// Block = 32 batch rows x 16 hidden units. Warp up owns units (j0g+2up, +1);
// lane ko owns k-chunk [16ko,16ko+16). Weights LDG'd (coalesced) per launch.
#define SCAN_SMEM (65536 + 6144)

__global__ __launch_bounds__(256, 1)
void gru_step(const unsigned int* __restrict__ resets,
              const float* __restrict__ bhn,
              float* __restrict__ out,
              int t)
{
    extern __shared__ __align__(16) unsigned char smraw[];
    float4* hsm = (float4*)smraw;              // [32 rows][128 float4] swizzled
    float*  xsm = (float*)(smraw + 65536);     // [32 rows][48]
    __shared__ unsigned int rfl[32];

    const int bx = blockIdx.x;
    const int rc = bx & 3, jc = bx >> 2;
    const int r0 = rc * 32, j0g = jc * 16;
    const int tid = threadIdx.x;
    const int up = tid >> 5;                   // warp id = unit pair
    const int ko = tid & 31;                   // lane = k-chunk
    const int u0 = j0g + 2 * up;

    // ---- weights: 24 coalesced LDG.128 per thread, in flight during staging
    ull w[48];
    {
        const ulonglong2* wp = (const ulonglong2*)(g_Wt + ((size_t)(jc * 256 + tid)) * 48);
#pragma unroll
        for (int i = 0; i < 24; i++) {
            ulonglong2 v = wp[i];
            w[2 * i] = v.x; w[2 * i + 1] = v.y;
        }
    }
    const float2 bh = *(const float2*)&bhn[u0];

    if (tid < 32) rfl[tid] = (t == 0) ? 1u : resets[(size_t)t * BATCH + r0 + tid];
    __syncthreads();

    // ---- stage h_prev (swizzled, coalesced, reset-masked) ----
    if (t == 0) {
        float4 z4 = make_float4(0.f, 0.f, 0.f, 0.f);
#pragma unroll
        for (int i = 0; i < 16; i++) {
            int j = i * 256 + tid, row = j >> 7, f = j & 127;
            hsm[row * 128 + SWZ(f)] = z4;
        }
    } else {
        const float* hp = out + (size_t)(t - 1) * (BATCH * HID) + (size_t)r0 * HID;
#pragma unroll
        for (int i = 0; i < 16; i++) {
            int j = i * 256 + tid, row = j >> 7, f = j & 127;
            float4 v = *(const float4*)(hp + (size_t)j * 4);
            if (rfl[row]) v = make_float4(0.f, 0.f, 0.f, 0.f);
            hsm[row * 128 + SWZ(f)] = v;
        }
    }
    // ---- stage this step's x gates: xsm[row][gate*16 + unit_local] ----
    const float* xb = g_xW + ((size_t)t * BATCH + r0) * GATES;
    {
        int idx = tid;                          // 384 float4s over 256 threads
        int row = idx / 12, q = idx - row * 12;
        float4 xv = *(const float4*)(xb + (size_t)row * GATES + (q >> 2) * HID + j0g + (q & 3) * 4);
        *(float4*)&xsm[row * 48 + q * 4] = xv;
        if (tid < 128) {
            idx = tid + 256; row = idx / 12; q = idx - row * 12;
            xv = *(const float4*)(xb + (size_t)row * GATES + (q >> 2) * HID + j0g + (q & 3) * 4);
            *(float4*)&xsm[row * 48 + q * 4] = xv;
        }
    }
    __syncthreads();

#pragma unroll 2
    for (int row = 0; row < 32; row++) {
        const float4* hr = hsm + row * 128;
        float4 h0 = hr[SWZ(4 * ko + 0)];
        float4 h1 = hr[SWZ(4 * ko + 1)];
        float4 h2 = hr[SWZ(4 * ko + 2)];
        float4 h3 = hr[SWZ(4 * ko + 3)];
        float ha[16] = {h0.x, h0.y, h0.z, h0.w, h1.x, h1.y, h1.z, h1.w,
                        h2.x, h2.y, h2.z, h2.w, h3.x, h3.y, h3.z, h3.w};
        ull ar_ = 0ull, az_ = 0ull, an_ = 0ull;
#pragma unroll
        for (int i = 0; i < 16; i++) {
            ull av = packf2(ha[i], ha[i]);
            fma2(ar_, av, w[i * 3 + 0]);
            fma2(az_, av, w[i * 3 + 1]);
            fma2(an_, av, w[i * 3 + 2]);
        }
        // warp all-reduce over the 32 k-chunks
#pragma unroll
        for (int m = 1; m < 32; m <<= 1) {
            addf2(ar_, shfl2(ar_, m));
            addf2(az_, shfl2(az_, m));
            addf2(an_, shfl2(an_, m));
        }
        // epilogue (redundant per lane; lane 0 stores)
        const float* xp = &xsm[row * 48 + 2 * up];
        float2 xr = *(const float2*)(xp);
        float2 xz = *(const float2*)(xp + 16);
        float2 xn = *(const float2*)(xp + 32);
        const float* hw = (const float*)(hr + SWZ(u0 >> 2));
        float2 hpv = *(const float2*)(hw + (u0 & 3));

        float sr0, sr1, sz0, sz1, sn0, sn1;
        unpackf2(ar_, sr0, sr1); unpackf2(az_, sz0, sz1); unpackf2(an_, sn0, sn1);
        float r0g = sigm(xr.x + sr0), r1g = sigm(xr.y + sr1);
        float z0g = sigm(xz.x + sz0), z1g = sigm(xz.y + sz1);
        float n0g = tanhx(xn.x + r0g * (sn0 + bh.x));
        float n1g = tanhx(xn.y + r1g * (sn1 + bh.y));
        float2 hnew;
        hnew.x = (1.0f - z0g) * n0g + z0g * hpv.x;
        hnew.y = (1.0f - z1g) * n1g + z1g * hpv.y;
        if (ko == 0)
            *(float2*)(out + ((size_t)t * BATCH + r0 + row) * HID + u0) = hnew;
    }
}

// ================================ Launch ===================================
extern "C" void kernel_launch(void* const* d_in, const int* in_sizes, int n_in,
                              void* d_out, int out_size)
{
    const float*        ins    = (const float*)d_in[0];
    const unsigned int* resets = (const unsigned int*)d_in[1];
    const float*        Wi     = (const float*)d_in[2];
    const float*        bi     = (const float*)d_in[3];
    const float*        Wh     = (const float*)d_in[4];
    const float*        bhn    = (const float*)d_in[5];
    float*              out    = (float*)d_out;

    prep_w<<<(32 * 256 * 48 + 255) / 256, 256>>>(Wh);

    dim3 g1(GATES / 128, MROWS / 128);
    xw_gemm<<<g1, 256>>>(ins, Wi, bi);

    cudaFuncSetAttribute(gru_step, cudaFuncAttributeMaxDynamicSharedMemorySize, SCAN_SMEM);
    for (int t = 0; t < T_STEPS; t++)
        gru_step<<<128, 256, SCAN_SMEM>>>(resets, bhn, out, t);
}

// round 8
// speedup vs baseline: 1.5873x; 1.4497x over previous
#include <cuda_runtime.h>
#include <math.h>

#define T_STEPS 512
#define BATCH   128
#define HID     512
#define GATES   1536
#define MROWS   (T_STEPS*BATCH)

__device__ float g_xW[(size_t)MROWS * GATES];   // 402 MB scratch
__device__ int          g_cnt4[4 * 32];          // per-row-group barrier state
__device__ volatile int g_sense4[4 * 32];

typedef unsigned long long ull;

__device__ __forceinline__ ull packf2(float lo, float hi) {
    ull r; asm("mov.b64 %0, {%1, %2};" : "=l"(r) : "f"(lo), "f"(hi)); return r;
}
__device__ __forceinline__ void unpackf2(ull v, float& lo, float& hi) {
    asm("mov.b64 {%0, %1}, %2;" : "=f"(lo), "=f"(hi) : "l"(v));
}
__device__ __forceinline__ void fma2(ull& acc, ull a, ull b) {
    asm("fma.rn.f32x2 %0, %1, %2, %0;" : "+l"(acc) : "l"(a), "l"(b));
}
__device__ __forceinline__ float sigm(float x)  { return 1.0f / (1.0f + __expf(-x)); }
__device__ __forceinline__ float tanhx(float x) { return 1.0f - 2.0f / (__expf(2.0f * x) + 1.0f); }

// ============================ Phase 1: xW GEMM =============================
__global__ __launch_bounds__(256, 2)
void xw_gemm(const float* __restrict__ A, const float* __restrict__ B,
             const float* __restrict__ bi)
{
    __shared__ __align__(16) float As[8][132];
    __shared__ __align__(16) float Bs[8][128];
    const int tid = threadIdx.x;
    const int mb = blockIdx.y * 128, nb = blockIdx.x * 128;
    const int arow = tid >> 1, ak = (tid & 1) * 4;
    const int brow = tid >> 5, bcol = (tid & 31) * 4;
    const int ty8 = (tid >> 4) * 8, tx8 = (tid & 15) * 8;

    ull acc[32];
#pragma unroll
    for (int i = 0; i < 32; i++) acc[i] = 0ull;

    const float* Ap = A + (size_t)(mb + arow) * HID + ak;
    const float* Bp = B + (size_t)brow * GATES + nb + bcol;

    for (int kt = 0; kt < 64; kt++) {
        float4 ra = *(const float4*)(Ap + kt * 8);
        float4 rb = *(const float4*)(Bp + (size_t)kt * 8 * GATES);
        As[ak + 0][arow] = ra.x; As[ak + 1][arow] = ra.y;
        As[ak + 2][arow] = ra.z; As[ak + 3][arow] = ra.w;
        *(float4*)&Bs[brow][bcol] = rb;
        __syncthreads();
#pragma unroll
        for (int kk = 0; kk < 8; kk++) {
            float4 a0 = *(const float4*)&As[kk][ty8];
            float4 a1 = *(const float4*)&As[kk][ty8 + 4];
            ulonglong2 b0 = *(const ulonglong2*)&Bs[kk][tx8];
            ulonglong2 b1 = *(const ulonglong2*)&Bs[kk][tx8 + 4];
            float ar[8] = {a0.x, a0.y, a0.z, a0.w, a1.x, a1.y, a1.z, a1.w};
#pragma unroll
            for (int i = 0; i < 8; i++) {
                ull av = packf2(ar[i], ar[i]);
                fma2(acc[i*4+0], av, b0.x); fma2(acc[i*4+1], av, b0.y);
                fma2(acc[i*4+2], av, b1.x); fma2(acc[i*4+3], av, b1.y);
            }
        }
        __syncthreads();
    }
    float4 c0 = *(const float4*)&bi[nb + tx8];
    float4 c1 = *(const float4*)&bi[nb + tx8 + 4];
#pragma unroll
    for (int i = 0; i < 8; i++) {
        float4 o0, o1;
        unpackf2(acc[i*4+0], o0.x, o0.y); unpackf2(acc[i*4+1], o0.z, o0.w);
        unpackf2(acc[i*4+2], o1.x, o1.y); unpackf2(acc[i*4+3], o1.z, o1.w);
        o0.x += c0.x; o0.y += c0.y; o0.z += c0.z; o0.w += c0.w;
        o1.x += c1.x; o1.y += c1.y; o1.z += c1.z; o1.w += c1.w;
        size_t off = (size_t)(mb + ty8 + i) * GATES + nb + tx8;
        *(float4*)&g_xW[off] = o0; *(float4*)&g_xW[off + 4] = o1;
    }
}

// ============================ Phase 2: GRU scan ============================
// Block = 32 batch rows x 16 hidden units, 256 threads: thread = (row, cu),
// row = tid>>3, cu = tid&7, units u0 = j0g + 2*cu (+1).
// Weight smem (gate-packed, conflict-free broadcast reads):
//   ws_rz[k*32 + cu*4]  : {Wr[u0], Wr[u0+1], Wz[u0], Wz[u0+1]}   (LDS.128/k)
//   ws_n [k2*32 + cu*4] : {Wn(2k2)[u0], Wn(2k2)[u0+1], Wn(2k2+1)[u0], ...}
//                                                                 (LDS.128/2k)
// h smem: hsm[row*516 + k], read as float4 per 4 k.
#define HSTR  516
#define F_RZ  (HID * 32)          // 16384 floats
#define F_N   (HID * 16)          // 8192 floats
#define F_H   (32 * HSTR)         // 16512 floats
#define SCAN_SMEM ((F_RZ + F_N + F_H) * 4)   // 164,352 B

__device__ __forceinline__ void groupbar(int rc) {
    __threadfence();
    __syncthreads();
    if (threadIdx.x == 0) {
        int* cnt = &g_cnt4[rc * 32];
        volatile int* sns = &g_sense4[rc * 32];
        int s = *sns;
        if (atomicAdd(cnt, 1) == 31) {
            *cnt = 0;
            __threadfence();
            *sns = s ^ 1;
        } else {
            while (*sns == s) { __nanosleep(32); }
        }
    }
    __syncthreads();
}

__global__ __launch_bounds__(256, 1)
void gru_scan(const unsigned int* __restrict__ resets,
              const float* __restrict__ Wh,
              const float* __restrict__ bhn,
              float* __restrict__ out)
{
    extern __shared__ __align__(16) float sm[];
    float* ws_rz = sm;                  // [512][32]
    float* ws_n  = sm + F_RZ;           // [256][32]
    float* hsm   = sm + F_RZ + F_N;     // [32][516]
    __shared__ unsigned int rfl[32];

    const int bx = blockIdx.x;
    const int rc = bx & 3, jc = bx >> 2;
    const int r0 = rc * 32, j0g = jc * 16;
    const int tid = threadIdx.x;
    const int row = tid >> 3, cu = tid & 7;
    const int u0 = j0g + 2 * cu;
    const int bglob = r0 + row;

    // ---- one-time: repack this block's Wh slice ----
    for (int idx = tid; idx < HID * 8; idx += 256) {
        int k = idx >> 3, c = idx & 7;
        int uu = j0g + 2 * c;
        const float* wk = Wh + (size_t)k * GATES;
        float* drz = &ws_rz[k * 32 + c * 4];
        drz[0] = wk[uu];           drz[1] = wk[uu + 1];
        drz[2] = wk[HID + uu];     drz[3] = wk[HID + uu + 1];
        // n weights: two k's packed per 16B
        ws_n[(k >> 1) * 32 + c * 4 + (k & 1) * 2 + 0] = wk[2 * HID + uu];
        ws_n[(k >> 1) * 32 + c * 4 + (k & 1) * 2 + 1] = wk[2 * HID + uu + 1];
    }
    const float2 bh = *(const float2*)&bhn[u0];
    if (tid < 32) rfl[tid] = 1u;        // t=0 behaves as reset
    __syncthreads();

    // prefetch x gates for t=0
    const float* x0 = g_xW + (size_t)bglob * GATES;
    float2 xr = *(const float2*)(x0 + u0);
    float2 xz = *(const float2*)(x0 + HID + u0);
    float2 xn = *(const float2*)(x0 + 2 * HID + u0);

    for (int t = 0; t < T_STEPS; t++) {
        // ---- stage h_prev into smem (coalesced, reset-masked) ----
        if (t == 0) {
            float4 z4 = make_float4(0.f, 0.f, 0.f, 0.f);
#pragma unroll
            for (int i = 0; i < 16; i++) {
                int j = i * 256 + tid;
                *(float4*)&hsm[(j >> 7) * HSTR + (j & 127) * 4] = z4;
            }
        } else {
            const float* hp = out + (size_t)(t - 1) * (BATCH * HID) + (size_t)r0 * HID;
#pragma unroll
            for (int i = 0; i < 16; i++) {
                int j = i * 256 + tid;
                float4 v = *(const float4*)(hp + (size_t)j * 4);
                if (rfl[j >> 7]) v = make_float4(0.f, 0.f, 0.f, 0.f);
                *(float4*)&hsm[(j >> 7) * HSTR + (j & 127) * 4] = v;
            }
        }
        __syncthreads();

        // ---- prefetch next step's x gates + reset flags ----
        float2 nxr = xr, nxz = xz, nxn = xn;
        if (t + 1 < T_STEPS) {
            const float* nx = g_xW + (size_t)((t + 1) * BATCH + bglob) * GATES;
            nxr = *(const float2*)(nx + u0);
            nxz = *(const float2*)(nx + HID + u0);
            nxn = *(const float2*)(nx + 2 * HID + u0);
            if (tid < 32) rfl[tid] = resets[(t + 1) * BATCH + r0 + tid];
        }

        // ---- recurrent GEMM: 6 pre-activations per thread ----
        ull accr = 0ull, accz = 0ull, accn = 0ull;
        const float* hr_ = &hsm[row * HSTR];
        const float* prz = ws_rz + cu * 4;
        const float* pn  = ws_n  + cu * 4;
#pragma unroll 2
        for (int k4 = 0; k4 < HID / 4; k4++) {
            float4 h4 = *(const float4*)(hr_ + k4 * 4);
            const float* wrz = prz + (k4 * 4) * 32;
            const float* wn  = pn  + (k4 * 2) * 32;
            ulonglong2 n01 = *(const ulonglong2*)(wn);
            ulonglong2 n23 = *(const ulonglong2*)(wn + 32);
            {
                ulonglong2 rz = *(const ulonglong2*)(wrz);
                ull av = packf2(h4.x, h4.x);
                fma2(accr, av, rz.x); fma2(accz, av, rz.y); fma2(accn, av, n01.x);
            }
            {
                ulonglong2 rz = *(const ulonglong2*)(wrz + 32);
                ull av = packf2(h4.y, h4.y);
                fma2(accr, av, rz.x); fma2(accz, av, rz.y); fma2(accn, av, n01.y);
            }
            {
                ulonglong2 rz = *(const ulonglong2*)(wrz + 64);
                ull av = packf2(h4.z, h4.z);
                fma2(accr, av, rz.x); fma2(accz, av, rz.y); fma2(accn, av, n23.x);
            }
            {
                ulonglong2 rz = *(const ulonglong2*)(wrz + 96);
                ull av = packf2(h4.w, h4.w);
                fma2(accr, av, rz.x); fma2(accz, av, rz.y); fma2(accn, av, n23.y);
            }
        }

        float sr0, sr1, sz0, sz1, sn0, sn1;
        unpackf2(accr, sr0, sr1); unpackf2(accz, sz0, sz1); unpackf2(accn, sn0, sn1);

        float2 hpv = *(const float2*)(hr_ + u0);
        float r0g = sigm(xr.x + sr0), r1g = sigm(xr.y + sr1);
        float z0g = sigm(xz.x + sz0), z1g = sigm(xz.y + sz1);
        float n0g = tanhx(xn.x + r0g * (sn0 + bh.x));
        float n1g = tanhx(xn.y + r1g * (sn1 + bh.y));
        float2 hnew;
        hnew.x = (1.0f - z0g) * n0g + z0g * hpv.x;
        hnew.y = (1.0f - z1g) * n1g + z1g * hpv.y;

        *(float2*)(out + ((size_t)t * BATCH + bglob) * HID + u0) = hnew;

        xr = nxr; xz = nxz; xn = nxn;

        groupbar(rc);
    }
}

// ================================ Launch ===================================
extern "C" void kernel_launch(void* const* d_in, const int* in_sizes, int n_in,
                              void* d_out, int out_size)
{
    const float*        ins    = (const float*)d_in[0];
    const unsigned int* resets = (const unsigned int*)d_in[1];
    const float*        Wi     = (const float*)d_in[2];
    const float*        bi     = (const float*)d_in[3];
    const float*        Wh     = (const float*)d_in[4];
    const float*        bhn    = (const float*)d_in[5];
    float*              out    = (float*)d_out;

    dim3 g1(GATES / 128, MROWS / 128);
    xw_gemm<<<g1, 256>>>(ins, Wi, bi);

    cudaFuncSetAttribute(gru_scan, cudaFuncAttributeMaxDynamicSharedMemorySize, SCAN_SMEM);
    gru_scan<<<128, 256, SCAN_SMEM>>>(resets, Wh, bhn, out);
}